// round 9
// baseline (speedup 1.0000x reference)
#include <cuda_runtime.h>
#include <cuda_fp16.h>
#include <cstdint>
#include <cstddef>

#define Bsz  64
#define Tlen 4096
#define DIN  64
#define DEMB 24
#define Hdim 128

// Scratch (static device globals — no allocation in kernel_launch)
__device__ float g_e[(size_t)Bsz * Tlen * DEMB];            // 25 MB
__device__ float g_u[(size_t)Bsz * Tlen * 4 * Hdim];        // 512 MB, layout [row][j*4+gate]

__device__ __forceinline__ float fsigmoid(float z) {
    return __fdividef(1.0f, 1.0f + __expf(-z));
}
__device__ __forceinline__ float ftanh(float z) {
    float e = __expf(-2.0f * z);
    return __fdividef(1.0f - e, 1.0f + e);
}

// ---------------------------------------------------------------------------
// K1: e[r][j] = sigmoid(x[r,:] @ W_emb[:,j] + b_emb[j]),  r in [0, B*T)
// ---------------------------------------------------------------------------
__global__ void __launch_bounds__(256) emb_kernel(
    const float* __restrict__ x,
    const float* __restrict__ W_emb,
    const float* __restrict__ b_emb)
{
    __shared__ float ws[DIN * DEMB];
    __shared__ float bs[DEMB];
    for (int i = threadIdx.x; i < DIN * DEMB; i += 256) ws[i] = W_emb[i];
    if (threadIdx.x < DEMB) bs[threadIdx.x] = b_emb[threadIdx.x];
    __syncthreads();

    size_t r = (size_t)blockIdx.x * 256 + threadIdx.x;   // grid sized exactly
    const float* xr = x + r * DIN;
    float xv[DIN];
#pragma unroll
    for (int d = 0; d < DIN; d += 4) {
        float4 v = *reinterpret_cast<const float4*>(xr + d);
        xv[d] = v.x; xv[d + 1] = v.y; xv[d + 2] = v.z; xv[d + 3] = v.w;
    }
    float* er = g_e + r * DEMB;
#pragma unroll 1
    for (int j = 0; j < DEMB; j++) {
        float acc = bs[j];
#pragma unroll
        for (int d = 0; d < DIN; d++) acc = fmaf(xv[d], ws[d * DEMB + j], acc);
        er[j] = fsigmoid(acc);
    }
}

// ---------------------------------------------------------------------------
// K2: u[r][j*4+g] = e[r,:] @ Wg[0:24, j] + bg[j]
//     Thread owns unit j (tid&127), ALL 4 gates (96 weight regs), 16 rows.
//     Writes one float4 {f,i,c,o} per (row, j) — fully coalesced.
// ---------------------------------------------------------------------------
__global__ void __launch_bounds__(256) ugemm_kernel(
    const float* __restrict__ Wf, const float* __restrict__ bf,
    const float* __restrict__ Wi, const float* __restrict__ bi,
    const float* __restrict__ Wc, const float* __restrict__ bc,
    const float* __restrict__ Wo, const float* __restrict__ bo)
{
    __shared__ float es[32][DEMB];
    size_t r0 = (size_t)blockIdx.x * 32;
    for (int i = threadIdx.x; i < 32 * DEMB; i += 256)
        es[i / DEMB][i % DEMB] = g_e[r0 * DEMB + i];
    __syncthreads();

    int tid = threadIdx.x;
    int j   = tid & 127;

    float wreg[4][DEMB];
#pragma unroll
    for (int d = 0; d < DEMB; d++) {
        wreg[0][d] = Wf[d * Hdim + j];
        wreg[1][d] = Wi[d * Hdim + j];
        wreg[2][d] = Wc[d * Hdim + j];
        wreg[3][d] = Wo[d * Hdim + j];
    }
    float bias[4] = { bf[j], bi[j], bc[j], bo[j] };

    int rbase = (tid >> 7) * 16;             // threads 0-127: rows 0-15; 128-255: rows 16-31
#pragma unroll 1
    for (int rr = 0; rr < 16; rr++) {
        int row = rbase + rr;
        float a0 = bias[0], a1 = bias[1], a2 = bias[2], a3 = bias[3];
#pragma unroll
        for (int d = 0; d < DEMB; d++) {
            float ev = es[row][d];
            a0 = fmaf(ev, wreg[0][d], a0);
            a1 = fmaf(ev, wreg[1][d], a1);
            a2 = fmaf(ev, wreg[2][d], a2);
            a3 = fmaf(ev, wreg[3][d], a3);
        }
        *reinterpret_cast<float4*>(g_u + (r0 + row) * 512 + j * 4)
            = make_float4(a0, a1, a2, a3);
    }
}

// ---------------------------------------------------------------------------
// K3: sequential scan. 64 CTAs (one per batch), 512 threads.
//     Warp w owns units [8w, 8w+8); lane l computes gate (l&3) of unit 8w+(l>>2).
//     Gate combine via 4 SHFLs inside the warp (no smem exchange, no 2nd phase).
//     ONE __syncthreads per step; h double-buffered as fp16 in smem.
//     Recurrent weights: 64 half2 registers per thread (fp32 accumulation).
// ---------------------------------------------------------------------------
__global__ void __launch_bounds__(512, 1) scan_kernel(
    const float* __restrict__ Wf, const float* __restrict__ Wi,
    const float* __restrict__ Wc, const float* __restrict__ Wo,
    const float* __restrict__ W_out, const float* __restrict__ b_out,
    float* __restrict__ out)
{
    const int b  = blockIdx.x;
    const int t  = threadIdx.x;
    const int l  = t & 31;
    const int w5 = t >> 5;
    const int j  = (w5 << 3) + (l >> 2);   // hidden unit 0..127
    const int g  = l & 3;                   // gate: 0=f 1=i 2=c(g) 3=o
    const unsigned FULL = 0xFFFFFFFFu;
    const int base = l & ~3;

    const float* Wg = g == 0 ? Wf : g == 1 ? Wi : g == 2 ? Wc : Wo;

    // Recurrent weights (rows 24..151, column j) packed into 64 half2 registers
    __half2 wr[64];
#pragma unroll
    for (int k = 0; k < 64; k++) {
        float w0 = Wg[(DEMB + 2 * k    ) * Hdim + j];
        float w1 = Wg[(DEMB + 2 * k + 1) * Hdim + j];
        wr[k] = __floats2half2_rn(w0, w1);
    }

    // activation constants: gate c uses tanh(z) = 2*sigmoid(2z) - 1
    const float sc = (g == 2) ? 2.f : 1.f;
    const float mm = (g == 2) ? 2.f : 1.f;
    const float aa = (g == 2) ? -1.f : 0.f;

    __shared__ __align__(16) __half hbuf[2][Hdim];
    __shared__ float hfin[Hdim];

    if (t < Hdim) hbuf[0][t] = __float2half_rn(0.f);
    float c = 0.f, hkeep = 0.f;

    const float* up = g_u + ((size_t)b * Tlen) * 512 + t;   // col == t (contiguous)
    float u_cur = up[0];
    __syncthreads();

    const __half2 z2 = __floats2half2_rn(0.f, 0.f);

    auto step = [&](int s, int p) {
        // prefetch next step's u (consumed ~600 cyc later)
        float u_nxt = 0.f;
        if (s + 1 < Tlen) u_nxt = up[(size_t)(s + 1) * 512];

        // GEMV over h (broadcast LDS.128), 4 chunked half2 accumulators
        const uint4* hp = reinterpret_cast<const uint4*>(hbuf[p]);
        __half2 a0 = z2, a1 = z2, a2 = z2, a3 = z2;
#pragma unroll
        for (int kk = 0; kk < 16; kk++) {
            union { uint4 v; __half2 h2[4]; } hv;
            hv.v = hp[kk];
            a0 = __hfma2(wr[kk * 4 + 0], hv.h2[0], a0);
            a1 = __hfma2(wr[kk * 4 + 1], hv.h2[1], a1);
            a2 = __hfma2(wr[kk * 4 + 2], hv.h2[2], a2);
            a3 = __hfma2(wr[kk * 4 + 3], hv.h2[3], a3);
        }
        float z = u_cur
                + __low2float(a0) + __high2float(a0)
                + __low2float(a1) + __high2float(a1)
                + __low2float(a2) + __high2float(a2)
                + __low2float(a3) + __high2float(a3);
        u_cur = u_nxt;

        // branch-free activation
        float ez = __expf(-sc * z);
        float gv = fmaf(mm, __fdividef(1.f, 1.f + ez), aa);

        // gate exchange within the quad (same warp) — no barrier needed
        float f_ = __shfl_sync(FULL, gv, base + 0);
        float i_ = __shfl_sync(FULL, gv, base + 1);
        float g_ = __shfl_sync(FULL, gv, base + 2);
        float o_ = __shfl_sync(FULL, gv, base + 3);

        // redundant cell update (identical in all 4 lanes of the quad)
        c = c * f_ + i_ * g_;
        float hn = ftanh(c) * o_;
        hkeep = hn;
        if (g == 0) hbuf[1 - p][j] = __float2half_rn(hn);
        __syncthreads();   // single barrier per step
    };

    for (int s = 0; s < Tlen; s += 2) {
        step(s, 0);
        step(s + 1, 1);
    }

    // final head: out[b] = sigmoid(h_T @ W_out + b_out)
    if (g == 0) hfin[j] = hkeep * W_out[j];
    __syncthreads();
    if (t == 0) {
        float sacc = b_out[0];
#pragma unroll 1
        for (int k = 0; k < Hdim; k++) sacc += hfin[k];
        out[b] = fsigmoid(sacc);
    }
}

// ---------------------------------------------------------------------------
// Launch
// inputs: 0:x 1:W_emb 2:b_emb 3:W_f 4:b_f 5:W_i 6:b_i 7:W_c 8:b_c
//         9:W_o 10:b_o 11:W_out 12:b_out
// ---------------------------------------------------------------------------
extern "C" void kernel_launch(void* const* d_in, const int* in_sizes, int n_in,
                              void* d_out, int out_size)
{
    const float* x     = (const float*)d_in[0];
    const float* W_emb = (const float*)d_in[1];
    const float* b_emb = (const float*)d_in[2];
    const float* W_f   = (const float*)d_in[3];
    const float* b_f   = (const float*)d_in[4];
    const float* W_i   = (const float*)d_in[5];
    const float* b_i   = (const float*)d_in[6];
    const float* W_c   = (const float*)d_in[7];
    const float* b_c   = (const float*)d_in[8];
    const float* W_o   = (const float*)d_in[9];
    const float* b_o   = (const float*)d_in[10];
    const float* W_out = (const float*)d_in[11];
    const float* b_out = (const float*)d_in[12];
    float* out = (float*)d_out;

    const int rows = Bsz * Tlen;                      // 262144

    emb_kernel<<<rows / 256, 256>>>(x, W_emb, b_emb);
    ugemm_kernel<<<rows / 32, 256>>>(W_f, b_f, W_i, b_i, W_c, b_c, W_o, b_o);
    scan_kernel<<<Bsz, 512>>>(W_f, W_i, W_c, W_o, W_out, b_out, out);
}

// round 10
// speedup vs baseline: 1.2094x; 1.2094x over previous
#include <cuda_runtime.h>
#include <cuda_fp16.h>
#include <cstdint>
#include <cstddef>

#define Bsz  64
#define Tlen 4096
#define DIN  64
#define DEMB 24
#define Hdim 128

// Scratch (static device globals — no allocation in kernel_launch)
__device__ float  g_e[(size_t)Bsz * Tlen * DEMB];              // 25 MB
__device__ __half g_u16[(size_t)Bsz * Tlen * 4 * Hdim];        // 256 MB, layout [row][j*4+gate]

__device__ __forceinline__ float tanhfast(float x) {
    float y;
    asm("tanh.approx.f32 %0, %1;" : "=f"(y) : "f"(x));
    return y;
}
__device__ __forceinline__ float fsigmoid(float z) {
    return fmaf(0.5f, tanhfast(0.5f * z), 0.5f);
}

// ---------------------------------------------------------------------------
// K1: e[r][j] = sigmoid(x[r,:] @ W_emb[:,j] + b_emb[j]),  r in [0, B*T)
//     24 register accumulators per thread; weights via broadcast LDS.128
//     (4 FMA per LDS -> FMA-bound instead of LSU-bound)
// ---------------------------------------------------------------------------
__global__ void __launch_bounds__(256) emb_kernel(
    const float* __restrict__ x,
    const float* __restrict__ W_emb,
    const float* __restrict__ b_emb)
{
    __shared__ float ws[DIN * DEMB];
    __shared__ float bs[DEMB];
    for (int i = threadIdx.x; i < DIN * DEMB; i += 256) ws[i] = W_emb[i];
    if (threadIdx.x < DEMB) bs[threadIdx.x] = b_emb[threadIdx.x];
    __syncthreads();

    size_t r = (size_t)blockIdx.x * 256 + threadIdx.x;   // grid sized exactly
    const float* xr = x + r * DIN;

    float acc[DEMB];
#pragma unroll
    for (int j = 0; j < DEMB; j++) acc[j] = bs[j];

#pragma unroll 1
    for (int d4 = 0; d4 < DIN; d4 += 4) {
        float4 xq = *reinterpret_cast<const float4*>(xr + d4);
        float xa[4] = { xq.x, xq.y, xq.z, xq.w };
#pragma unroll
        for (int q = 0; q < 4; q++) {
            // row (d4+q) of ws: 24 floats, 96 B, 16B-aligned
            const float4* wp = reinterpret_cast<const float4*>(ws + (d4 + q) * DEMB);
#pragma unroll
            for (int m = 0; m < 6; m++) {
                float4 wv = wp[m];
                acc[m * 4 + 0] = fmaf(xa[q], wv.x, acc[m * 4 + 0]);
                acc[m * 4 + 1] = fmaf(xa[q], wv.y, acc[m * 4 + 1]);
                acc[m * 4 + 2] = fmaf(xa[q], wv.z, acc[m * 4 + 2]);
                acc[m * 4 + 3] = fmaf(xa[q], wv.w, acc[m * 4 + 3]);
            }
        }
    }

    float* er = g_e + r * DEMB;
#pragma unroll
    for (int j = 0; j < DEMB; j++) er[j] = fsigmoid(acc[j]);
}

// ---------------------------------------------------------------------------
// K2: u[r][j*4+g] = e[r,:] @ Wg[0:24, j] + bg[j]   (stored as fp16)
//     Thread owns unit j (tid&127), ALL 4 gates (96 weight regs), 16 rows.
//     Writes one uint2 (4 halves {f,i,c,o}) per (row, j) — coalesced.
// ---------------------------------------------------------------------------
__global__ void __launch_bounds__(256) ugemm_kernel(
    const float* __restrict__ Wf, const float* __restrict__ bf,
    const float* __restrict__ Wi, const float* __restrict__ bi,
    const float* __restrict__ Wc, const float* __restrict__ bc,
    const float* __restrict__ Wo, const float* __restrict__ bo)
{
    __shared__ float es[32][DEMB];
    size_t r0 = (size_t)blockIdx.x * 32;
    for (int i = threadIdx.x; i < 32 * DEMB; i += 256)
        es[i / DEMB][i % DEMB] = g_e[r0 * DEMB + i];
    __syncthreads();

    int tid = threadIdx.x;
    int j   = tid & 127;

    float wreg[4][DEMB];
#pragma unroll
    for (int d = 0; d < DEMB; d++) {
        wreg[0][d] = Wf[d * Hdim + j];
        wreg[1][d] = Wi[d * Hdim + j];
        wreg[2][d] = Wc[d * Hdim + j];
        wreg[3][d] = Wo[d * Hdim + j];
    }
    float bias[4] = { bf[j], bi[j], bc[j], bo[j] };

    int rbase = (tid >> 7) * 16;             // threads 0-127: rows 0-15; 128-255: rows 16-31
#pragma unroll 1
    for (int rr = 0; rr < 16; rr++) {
        int row = rbase + rr;
        float a0 = bias[0], a1 = bias[1], a2 = bias[2], a3 = bias[3];
#pragma unroll
        for (int d = 0; d < DEMB; d++) {
            float ev = es[row][d];
            a0 = fmaf(ev, wreg[0][d], a0);
            a1 = fmaf(ev, wreg[1][d], a1);
            a2 = fmaf(ev, wreg[2][d], a2);
            a3 = fmaf(ev, wreg[3][d], a3);
        }
        __half2 lo = __floats2half2_rn(a0, a1);
        __half2 hi = __floats2half2_rn(a2, a3);
        uint2 v;
        v.x = *reinterpret_cast<uint32_t*>(&lo);
        v.y = *reinterpret_cast<uint32_t*>(&hi);
        *reinterpret_cast<uint2*>(g_u16 + ((r0 + row) * 512 + j * 4)) = v;
    }
}

// ---------------------------------------------------------------------------
// K3: sequential scan. 64 CTAs (one per batch), 512 threads.
//     Warp w owns units [8w, 8w+8); lane l computes gate (l&3) of unit 8w+(l>>2).
//     Gate combine via 4 SHFLs inside the warp; ONE __syncthreads per step.
//     Recurrent weights: 64 half2 registers/thread; fp16 chunked accumulation.
//     Activations via single-instruction tanh.approx.f32.
//     u prefetched 2 steps deep as raw __half.
// ---------------------------------------------------------------------------
__global__ void __launch_bounds__(512, 1) scan_kernel(
    const float* __restrict__ Wf, const float* __restrict__ Wi,
    const float* __restrict__ Wc, const float* __restrict__ Wo,
    const float* __restrict__ W_out, const float* __restrict__ b_out,
    float* __restrict__ out)
{
    const int b  = blockIdx.x;
    const int t  = threadIdx.x;
    const int l  = t & 31;
    const int w5 = t >> 5;
    const int j  = (w5 << 3) + (l >> 2);   // hidden unit 0..127
    const int g  = l & 3;                   // gate: 0=f 1=i 2=c(g) 3=o
    const unsigned FULL = 0xFFFFFFFFu;
    const int base = l & ~3;

    const float* Wg = g == 0 ? Wf : g == 1 ? Wi : g == 2 ? Wc : Wo;

    // Recurrent weights (rows 24..151, column j) packed into 64 half2 registers
    __half2 wr[64];
#pragma unroll
    for (int k = 0; k < 64; k++) {
        float w0 = Wg[(DEMB + 2 * k    ) * Hdim + j];
        float w1 = Wg[(DEMB + 2 * k + 1) * Hdim + j];
        wr[k] = __floats2half2_rn(w0, w1);
    }

    // activation: gate c uses tanh(z); others sigmoid(z) = 0.5*tanh(0.5z)+0.5
    const float sc = (g == 2) ? 1.f  : 0.5f;
    const float mm = (g == 2) ? 1.f  : 0.5f;
    const float aa = (g == 2) ? 0.f  : 0.5f;

    __shared__ __align__(16) __half hbuf[2][Hdim];
    __shared__ float hfin[Hdim];

    if (t < Hdim) hbuf[0][t] = __float2half_rn(0.f);
    float c = 0.f, hkeep = 0.f;

    const __half* up = g_u16 + ((size_t)b * Tlen) * 512 + t;   // col == t
    float  u_cur = __half2float(up[0]);
    __half u_n1  = up[512];
    __half u_n2  = up[1024];
    __syncthreads();

    const __half2 z2 = __floats2half2_rn(0.f, 0.f);

    auto step = [&](int s, int p) {
        // prefetch u for step s+3 (consumed ~2.5 steps later)
        __half u_n3 = __float2half_rn(0.f);
        if (s + 3 < Tlen) u_n3 = up[(size_t)(s + 3) * 512];

        // GEMV over h (broadcast LDS.128), 4 chunked half2 accumulators
        const uint4* hp = reinterpret_cast<const uint4*>(hbuf[p]);
        __half2 a0 = z2, a1 = z2, a2 = z2, a3 = z2;
#pragma unroll
        for (int kk = 0; kk < 16; kk++) {
            union { uint4 v; __half2 h2[4]; } hv;
            hv.v = hp[kk];
            a0 = __hfma2(wr[kk * 4 + 0], hv.h2[0], a0);
            a1 = __hfma2(wr[kk * 4 + 1], hv.h2[1], a1);
            a2 = __hfma2(wr[kk * 4 + 2], hv.h2[2], a2);
            a3 = __hfma2(wr[kk * 4 + 3], hv.h2[3], a3);
        }
        // short reduction: 2 HADD2 + 2 H2F2 + 3 FADD
        __half2 b0 = __hadd2(a0, a1);
        __half2 b1 = __hadd2(a2, a3);
        float2 f0 = __half22float2(b0);
        float2 f1 = __half22float2(b1);
        float z = ((u_cur + f0.x) + f0.y) + (f1.x + f1.y);

        // shift the u pipeline
        u_cur = __half2float(u_n1);
        u_n1  = u_n2;
        u_n2  = u_n3;

        // branch-free activation (1 MUFU.TANH)
        float gv = fmaf(mm, tanhfast(sc * z), aa);

        // gate exchange within the quad (same warp) — no barrier needed
        float f_ = __shfl_sync(FULL, gv, base + 0);
        float i_ = __shfl_sync(FULL, gv, base + 1);
        float g_ = __shfl_sync(FULL, gv, base + 2);
        float o_ = __shfl_sync(FULL, gv, base + 3);

        // redundant cell update (identical in all 4 lanes of the quad)
        c = fmaf(c, f_, i_ * g_);
        float hn = tanhfast(c) * o_;
        hkeep = hn;
        if (g == 0) hbuf[1 - p][j] = __float2half_rn(hn);
        __syncthreads();   // single barrier per step
    };

#pragma unroll 1
    for (int s = 0; s < Tlen; s += 2) {
        step(s, 0);
        step(s + 1, 1);
    }

    // final head: out[b] = sigmoid(h_T @ W_out + b_out)
    if (g == 0) hfin[j] = hkeep * W_out[j];
    __syncthreads();
    if (t == 0) {
        float sacc = b_out[0];
#pragma unroll 1
        for (int k = 0; k < Hdim; k++) sacc += hfin[k];
        out[b] = fsigmoid(sacc);
    }
}

// ---------------------------------------------------------------------------
// Launch
// inputs: 0:x 1:W_emb 2:b_emb 3:W_f 4:b_f 5:W_i 6:b_i 7:W_c 8:b_c
//         9:W_o 10:b_o 11:W_out 12:b_out
// ---------------------------------------------------------------------------
extern "C" void kernel_launch(void* const* d_in, const int* in_sizes, int n_in,
                              void* d_out, int out_size)
{
    const float* x     = (const float*)d_in[0];
    const float* W_emb = (const float*)d_in[1];
    const float* b_emb = (const float*)d_in[2];
    const float* W_f   = (const float*)d_in[3];
    const float* b_f   = (const float*)d_in[4];
    const float* W_i   = (const float*)d_in[5];
    const float* b_i   = (const float*)d_in[6];
    const float* W_c   = (const float*)d_in[7];
    const float* b_c   = (const float*)d_in[8];
    const float* W_o   = (const float*)d_in[9];
    const float* b_o   = (const float*)d_in[10];
    const float* W_out = (const float*)d_in[11];
    const float* b_out = (const float*)d_in[12];
    float* out = (float*)d_out;

    const int rows = Bsz * Tlen;                      // 262144

    emb_kernel<<<rows / 256, 256>>>(x, W_emb, b_emb);
    ugemm_kernel<<<rows / 32, 256>>>(W_f, b_f, W_i, b_i, W_c, b_c, W_o, b_o);
    scan_kernel<<<Bsz, 512>>>(W_f, W_i, W_c, W_o, W_out, b_out, out);
}